// round 1
// baseline (speedup 1.0000x reference)
#include <cuda_runtime.h>
#include <math.h>

#define DM   512
#define DFF  2048
#define NH   8
#define DH   64
#define BB   2
#define SEQ  2048
#define ROWS (BB*SEQ)   // 4096

// ---------------- static scratch (no allocations allowed) ----------------
__device__ float g_Q [ROWS*DM];
__device__ float g_K [ROWS*DM];
__device__ float g_V [ROWS*DM];
__device__ float g_O [ROWS*DM];
__device__ float g_T [ROWS*DM];
__device__ float g_Z [ROWS*DM];
__device__ float g_H1[ROWS*DFF];

// =====================================================================
// Generic tiled SGEMM: C[M,N] = A[M,K] @ B(K,N) (+bias)(+residual)(relu)
// BM=BN=64, BK=16, 256 threads, 4x4 microtile per thread.
// HEADED: B is [H, K, 64] stacked per-head weights, col n -> (h=n>>6, e=n&63)
// =====================================================================
template<bool HEADED, bool BIAS, bool RELU, bool RES>
__global__ void __launch_bounds__(256) gemm_kernel(
    const float* __restrict__ A, const float* __restrict__ B,
    const float* __restrict__ bias, const float* __restrict__ R,
    float* __restrict__ C, int M, int N, int K)
{
    __shared__ float As[16][68];   // transposed: As[k][m], padded
    __shared__ float Bs[16][64];   // Bs[k][n]

    const int tid = threadIdx.x;
    const int tx  = tid & 15;       // 0..15 -> 4 cols each
    const int ty  = tid >> 4;       // 0..15 -> 4 rows each
    const int n0  = blockIdx.x * 64;
    const int m0  = blockIdx.y * 64;

    const int arow = tid >> 2;          // 0..63
    const int akc  = (tid & 3) << 2;    // 0,4,8,12
    const int bk   = tid >> 4;          // 0..15
    const int bn   = (tid & 15) << 2;   // 0..60

    float acc[4][4] = {};

    for (int k0 = 0; k0 < K; k0 += 16) {
        float4 av = *(const float4*)(A + (size_t)(m0 + arow) * K + k0 + akc);
        float4 bv;
        if (HEADED) {
            int n = n0 + bn;
            bv = *(const float4*)(B + (size_t)(n >> 6) * K * 64
                                    + (size_t)(k0 + bk) * 64 + (n & 63));
        } else {
            bv = *(const float4*)(B + (size_t)(k0 + bk) * N + n0 + bn);
        }
        As[akc + 0][arow] = av.x;
        As[akc + 1][arow] = av.y;
        As[akc + 2][arow] = av.z;
        As[akc + 3][arow] = av.w;
        *(float4*)&Bs[bk][bn] = bv;
        __syncthreads();

#pragma unroll
        for (int k = 0; k < 16; k++) {
            float4 a = *(const float4*)&As[k][ty << 2];
            float4 b = *(const float4*)&Bs[k][tx << 2];
            acc[0][0] += a.x * b.x; acc[0][1] += a.x * b.y; acc[0][2] += a.x * b.z; acc[0][3] += a.x * b.w;
            acc[1][0] += a.y * b.x; acc[1][1] += a.y * b.y; acc[1][2] += a.y * b.z; acc[1][3] += a.y * b.w;
            acc[2][0] += a.z * b.x; acc[2][1] += a.z * b.y; acc[2][2] += a.z * b.z; acc[2][3] += a.z * b.w;
            acc[3][0] += a.w * b.x; acc[3][1] += a.w * b.y; acc[3][2] += a.w * b.z; acc[3][3] += a.w * b.w;
        }
        __syncthreads();
    }

    float4 bz = make_float4(0.f, 0.f, 0.f, 0.f);
    if (BIAS) bz = *(const float4*)(bias + n0 + (tx << 2));

#pragma unroll
    for (int ii = 0; ii < 4; ii++) {
        int m = m0 + (ty << 2) + ii;
        float4 v = make_float4(acc[ii][0], acc[ii][1], acc[ii][2], acc[ii][3]);
        if (BIAS) { v.x += bz.x; v.y += bz.y; v.z += bz.z; v.w += bz.w; }
        if (RES) {
            float4 r = *(const float4*)(R + (size_t)m * N + n0 + (tx << 2));
            v.x += r.x; v.y += r.y; v.z += r.z; v.w += r.w;
        }
        if (RELU) {
            v.x = fmaxf(v.x, 0.f); v.y = fmaxf(v.y, 0.f);
            v.z = fmaxf(v.z, 0.f); v.w = fmaxf(v.w, 0.f);
        }
        *(float4*)(C + (size_t)m * N + n0 + (tx << 2)) = v;
    }
}

// =====================================================================
// Flash attention (fp32, non-causal), one CTA per (b, h, 64-query tile).
// Q/K/V layout: [row = b*SEQ+s][h*64+e], i.e. [B,S,H,DH] flattened.
// =====================================================================
#define ALD 65   // padded leading dim for smem tiles
#define ATTN_SMEM_FLOATS (4*64*ALD + 3*64)
#define ATTN_SMEM_BYTES  (ATTN_SMEM_FLOATS*4)

__global__ void __launch_bounds__(256) attn_kernel(
    const float* __restrict__ Q, const float* __restrict__ K,
    const float* __restrict__ V, float* __restrict__ O)
{
    const int s0 = blockIdx.x * 64;
    const int h  = blockIdx.y;
    const int b  = blockIdx.z;

    extern __shared__ float sm[];
    float* Qs = sm;                 // [64][ALD]
    float* Ks = Qs + 64 * ALD;      // [64][ALD]
    float* Vs = Ks + 64 * ALD;      // [64][ALD]
    float* Ps = Vs + 64 * ALD;      // [64][ALD]
    float* rm = Ps + 64 * ALD;      // [64] row max
    float* rl = rm + 64;            // [64] row sum
    float* rc = rl + 64;            // [64] correction factor

    const int tid = threadIdx.x;
    const int tx  = tid & 15;
    const int ty  = tid >> 4;
    const size_t base = (size_t)b * SEQ * DM + (size_t)h * DH;

    // load Q tile (64 rows x 64 dims)
    {
        int r = tid >> 4, c = (tid & 15) << 2;
#pragma unroll
        for (int p = 0; p < 4; p++) {
            int row = r + p * 16;
            float4 v = *(const float4*)(Q + base + (size_t)(s0 + row) * DM + c);
            Qs[row * ALD + c + 0] = v.x;
            Qs[row * ALD + c + 1] = v.y;
            Qs[row * ALD + c + 2] = v.z;
            Qs[row * ALD + c + 3] = v.w;
        }
    }
    if (tid < 64) { rm[tid] = -1e30f; rl[tid] = 0.f; }

    float o[4][4] = {};

    for (int j0 = 0; j0 < SEQ; j0 += 64) {
        __syncthreads();  // protect Vs/Ps/rc from previous round
        {
            int r = tid >> 4, c = (tid & 15) << 2;
#pragma unroll
            for (int p = 0; p < 4; p++) {
                int row = r + p * 16;
                float4 kv = *(const float4*)(K + base + (size_t)(j0 + row) * DM + c);
                Ks[row * ALD + c + 0] = kv.x;
                Ks[row * ALD + c + 1] = kv.y;
                Ks[row * ALD + c + 2] = kv.z;
                Ks[row * ALD + c + 3] = kv.w;
                float4 vv = *(const float4*)(V + base + (size_t)(j0 + row) * DM + c);
                Vs[row * ALD + c + 0] = vv.x;
                Vs[row * ALD + c + 1] = vv.y;
                Vs[row * ALD + c + 2] = vv.z;
                Vs[row * ALD + c + 3] = vv.w;
            }
        }
        __syncthreads();

        // S = (Q K^T) * scale, 4x4 per thread
        float s[4][4] = {};
#pragma unroll 8
        for (int k = 0; k < 64; k++) {
            float a0 = Qs[(ty * 4 + 0) * ALD + k];
            float a1 = Qs[(ty * 4 + 1) * ALD + k];
            float a2 = Qs[(ty * 4 + 2) * ALD + k];
            float a3 = Qs[(ty * 4 + 3) * ALD + k];
            float b0 = Ks[(tx * 4 + 0) * ALD + k];
            float b1 = Ks[(tx * 4 + 1) * ALD + k];
            float b2 = Ks[(tx * 4 + 2) * ALD + k];
            float b3 = Ks[(tx * 4 + 3) * ALD + k];
            s[0][0] += a0 * b0; s[0][1] += a0 * b1; s[0][2] += a0 * b2; s[0][3] += a0 * b3;
            s[1][0] += a1 * b0; s[1][1] += a1 * b1; s[1][2] += a1 * b2; s[1][3] += a1 * b3;
            s[2][0] += a2 * b0; s[2][1] += a2 * b1; s[2][2] += a2 * b2; s[2][3] += a2 * b3;
            s[3][0] += a3 * b0; s[3][1] += a3 * b1; s[3][2] += a3 * b2; s[3][3] += a3 * b3;
        }
#pragma unroll
        for (int ii = 0; ii < 4; ii++)
#pragma unroll
            for (int jj = 0; jj < 4; jj++)
                Ps[(ty * 4 + ii) * ALD + tx * 4 + jj] = s[ii][jj] * 0.125f;
        __syncthreads();

        // online softmax row pass (threads 0..63, one row each)
        if (tid < 64) {
            float m_old = rm[tid];
            float mx = m_old;
#pragma unroll 8
            for (int j = 0; j < 64; j++) mx = fmaxf(mx, Ps[tid * ALD + j]);
            float cf = __expf(m_old - mx);
            float l  = rl[tid] * cf;
#pragma unroll 8
            for (int j = 0; j < 64; j++) {
                float p = __expf(Ps[tid * ALD + j] - mx);
                Ps[tid * ALD + j] = p;
                l += p;
            }
            rm[tid] = mx; rl[tid] = l; rc[tid] = cf;
        }
        __syncthreads();

        // O = O*c + P @ V
        float c0 = rc[ty * 4 + 0], c1 = rc[ty * 4 + 1];
        float c2 = rc[ty * 4 + 2], c3 = rc[ty * 4 + 3];
#pragma unroll
        for (int jj = 0; jj < 4; jj++) {
            o[0][jj] *= c0; o[1][jj] *= c1; o[2][jj] *= c2; o[3][jj] *= c3;
        }
#pragma unroll 8
        for (int j = 0; j < 64; j++) {
            float a0 = Ps[(ty * 4 + 0) * ALD + j];
            float a1 = Ps[(ty * 4 + 1) * ALD + j];
            float a2 = Ps[(ty * 4 + 2) * ALD + j];
            float a3 = Ps[(ty * 4 + 3) * ALD + j];
            float b0 = Vs[j * ALD + tx * 4 + 0];
            float b1 = Vs[j * ALD + tx * 4 + 1];
            float b2 = Vs[j * ALD + tx * 4 + 2];
            float b3 = Vs[j * ALD + tx * 4 + 3];
            o[0][0] += a0 * b0; o[0][1] += a0 * b1; o[0][2] += a0 * b2; o[0][3] += a0 * b3;
            o[1][0] += a1 * b0; o[1][1] += a1 * b1; o[1][2] += a1 * b2; o[1][3] += a1 * b3;
            o[2][0] += a2 * b0; o[2][1] += a2 * b1; o[2][2] += a2 * b2; o[2][3] += a2 * b3;
            o[3][0] += a3 * b0; o[3][1] += a3 * b1; o[3][2] += a3 * b2; o[3][3] += a3 * b3;
        }
    }
    __syncthreads();

#pragma unroll
    for (int ii = 0; ii < 4; ii++) {
        float inv = 1.f / rl[ty * 4 + ii];
        float4 v = make_float4(o[ii][0] * inv, o[ii][1] * inv, o[ii][2] * inv, o[ii][3] * inv);
        *(float4*)(O + base + (size_t)(s0 + ty * 4 + ii) * DM + tx * 4) = v;
    }
}

// =====================================================================
// LayerNorm over 512-element rows. block = 128 threads, float4 each.
// =====================================================================
__global__ void __launch_bounds__(128) ln_kernel(
    const float* __restrict__ X, const float* __restrict__ g,
    const float* __restrict__ be, float* __restrict__ Y)
{
    const int row = blockIdx.x;
    const int tid = threadIdx.x;
    const float* x = X + (size_t)row * DM;

    float4 v = *(const float4*)(x + (tid << 2));
    float s = v.x + v.y + v.z + v.w;
    float q = v.x * v.x + v.y * v.y + v.z * v.z + v.w * v.w;
#pragma unroll
    for (int o = 16; o; o >>= 1) {
        s += __shfl_xor_sync(0xFFFFFFFFu, s, o);
        q += __shfl_xor_sync(0xFFFFFFFFu, q, o);
    }
    __shared__ float ss[4], qq[4];
    if ((tid & 31) == 0) { ss[tid >> 5] = s; qq[tid >> 5] = q; }
    __syncthreads();
    s = ss[0] + ss[1] + ss[2] + ss[3];
    q = qq[0] + qq[1] + qq[2] + qq[3];
    float mean = s * (1.f / DM);
    float var  = q * (1.f / DM) - mean * mean;
    float rstd = rsqrtf(var + 1e-5f);

    float4 gv = *(const float4*)(g  + (tid << 2));
    float4 bv = *(const float4*)(be + (tid << 2));
    float4 y;
    y.x = (v.x - mean) * rstd * gv.x + bv.x;
    y.y = (v.y - mean) * rstd * gv.y + bv.y;
    y.z = (v.z - mean) * rstd * gv.z + bv.z;
    y.w = (v.w - mean) * rstd * gv.w + bv.w;
    *(float4*)(Y + (size_t)row * DM + (tid << 2)) = y;
}

// =====================================================================
extern "C" void kernel_launch(void* const* d_in, const int* in_sizes, int n_in,
                              void* d_out, int out_size)
{
    const float* z_in = (const float*)d_in[0];
    const float* Wq = (const float*)d_in[1];
    const float* bq = (const float*)d_in[2];
    const float* Wk = (const float*)d_in[3];
    const float* bk = (const float*)d_in[4];
    const float* Wv = (const float*)d_in[5];
    const float* bv = (const float*)d_in[6];
    const float* Wo = (const float*)d_in[7];
    const float* bo = (const float*)d_in[8];
    const float* W1 = (const float*)d_in[9];
    const float* b1 = (const float*)d_in[10];
    const float* W2 = (const float*)d_in[11];
    const float* b2 = (const float*)d_in[12];
    const float* g1 = (const float*)d_in[13];
    const float* be1 = (const float*)d_in[14];
    const float* g2 = (const float*)d_in[15];
    const float* be2 = (const float*)d_in[16];
    float* out = (float*)d_out;

    float *Qb, *Kb, *Vb, *Ob, *Tb, *Zb, *H1b;
    cudaGetSymbolAddress((void**)&Qb, g_Q);
    cudaGetSymbolAddress((void**)&Kb, g_K);
    cudaGetSymbolAddress((void**)&Vb, g_V);
    cudaGetSymbolAddress((void**)&Ob, g_O);
    cudaGetSymbolAddress((void**)&Tb, g_T);
    cudaGetSymbolAddress((void**)&Zb, g_Z);
    cudaGetSymbolAddress((void**)&H1b, g_H1);

    cudaFuncSetAttribute(attn_kernel,
        cudaFuncAttributeMaxDynamicSharedMemorySize, ATTN_SMEM_BYTES);

    dim3 blk(256);
    dim3 gDM(DM / 64, ROWS / 64);      // N=512 output GEMMs
    dim3 gFF(DFF / 64, ROWS / 64);     // N=2048 output GEMM
    dim3 gAttn(SEQ / 64, NH, BB);

    for (int it = 0; it < 4; it++) {
        const float* z = (it == 0) ? z_in : Zb;

        // QKV projections (headed weights [H, D, DH])
        gemm_kernel<true, true, false, false><<<gDM, blk>>>(z, Wq, bq, nullptr, Qb, ROWS, DM, DM);
        gemm_kernel<true, true, false, false><<<gDM, blk>>>(z, Wk, bk, nullptr, Kb, ROWS, DM, DM);
        gemm_kernel<true, true, false, false><<<gDM, blk>>>(z, Wv, bv, nullptr, Vb, ROWS, DM, DM);

        // attention
        attn_kernel<<<gAttn, blk, ATTN_SMEM_BYTES>>>(Qb, Kb, Vb, Ob);

        // output projection + bias + residual(z) -> T
        gemm_kernel<false, true, false, true><<<gDM, blk>>>(Ob, Wo, bo, z, Tb, ROWS, DM, DM);

        // LN1 -> z (or final output on last iteration; FFN+LN2 of iter 3 are dead code)
        float* lnout = (it == 3) ? out : Zb;
        ln_kernel<<<ROWS, 128>>>(Tb, g1, be1, lnout);

        if (it < 3) {
            // FFN: H1 = relu(z @ W1 + b1); T = H1 @ W2 + b2 + z; z = LN2(T)
            gemm_kernel<false, true, true, false><<<gFF, blk>>>(Zb, W1, b1, nullptr, H1b, ROWS, DFF, DM);
            gemm_kernel<false, true, false, true><<<gDM, blk>>>(H1b, W2, b2, Zb, Tb, ROWS, DM, DFF);
            ln_kernel<<<ROWS, 128>>>(Tb, g2, be2, Zb);
        }
    }
}

// round 3
// speedup vs baseline: 1.7100x; 1.7100x over previous
#include <cuda_runtime.h>
#include <cstdint>
#include <math.h>

#define DM   512
#define DFF  2048
#define NH   8
#define DH   64
#define BB   2
#define SEQ  2048
#define ROWS (BB*SEQ)   // 4096

// ---------------- static scratch (no allocations allowed) ----------------
__device__ float g_Q  [ROWS*DM];
__device__ float g_K  [ROWS*DM];
__device__ float g_V  [ROWS*DM];
__device__ float g_O  [ROWS*DM];
__device__ float g_T  [ROWS*DM];
__device__ float g_Z  [ROWS*DM];
__device__ float g_H1 [ROWS*DFF];
__device__ float g_WqT[DM*DM];
__device__ float g_WkT[DM*DM];
__device__ float g_WvT[DM*DM];
__device__ float g_WoT[DM*DM];
__device__ float g_W1T[DFF*DM];
__device__ float g_W2T[DM*DFF];

__device__ __forceinline__ uint32_t f2tf32(float f) {
    uint32_t r;
    asm("cvt.rna.tf32.f32 %0, %1;" : "=r"(r) : "f"(f));
    return r;
}

#define MMA_TF32(d0,d1,d2,d3, a0,a1,a2,a3, b0,b1) \
    asm volatile("mma.sync.aligned.m16n8k8.row.col.f32.tf32.tf32.f32 " \
        "{%0,%1,%2,%3}, {%4,%5,%6,%7}, {%8,%9}, {%0,%1,%2,%3};" \
        : "+f"(d0), "+f"(d1), "+f"(d2), "+f"(d3) \
        : "r"(a0), "r"(a1), "r"(a2), "r"(a3), "r"(b0), "r"(b1))

// =====================================================================
// Weight pre-transpose kernels (run once per call, ~5us total)
// =====================================================================
// headed: W [H, K=512, 64] -> out[n][k], n = h*64+e
__global__ void headed_T_kernel(const float* __restrict__ W, float* __restrict__ out) {
    int idx = blockIdx.x * 256 + threadIdx.x;            // over 512*512
    int n = idx >> 9, k = idx & 511;
    out[idx] = W[(size_t)(n >> 6) * (512 * 64) + (size_t)k * 64 + (n & 63)];
}
// generic: in [R,C] -> out [C,R]
__global__ void matT_kernel(const float* __restrict__ in, float* __restrict__ out, int R, int C) {
    int idx = blockIdx.x * 256 + threadIdx.x;
    if (idx >= R * C) return;
    int c = idx / R, r = idx - c * R;
    out[idx] = in[(size_t)r * C + c];
}

// =====================================================================
// TF32 mma.sync GEMM: C[M,N] = A[M,K] @ BT[N,K]^T + bias (+res)(+relu)
// CTA 128x128, K-slab 32, double-buffered smem with register prefetch.
// 8 warps: wm = wid&1 (64 rows), wn = wid>>1 (32 cols). Warp tile 64x32.
// Smem tiles [128][32] tf32, XOR-swizzled: elem (r,c) at r*32 + (c ^ ((r&7)<<2)).
// =====================================================================
#define G_SMEM_BYTES (2 * 2 * 128 * 32 * 4)   // 65536

template<bool RELU, bool RES>
__global__ void __launch_bounds__(256) mma_gemm(
    const float* __restrict__ A, const float* __restrict__ BT,
    const float* __restrict__ bias, const float* __restrict__ R,
    float* __restrict__ C, int M, int N, int K)
{
    extern __shared__ uint32_t sm[];
    uint32_t* Asm = sm;                 // [2][4096]
    uint32_t* Bsm = sm + 8192;          // [2][4096]

    const int tid = threadIdx.x;
    const int wid = tid >> 5, l = tid & 31;
    const int lr  = l >> 2, la = l & 3;
    const int sx  = lr << 2;
    const int wm  = wid & 1;            // 0..1
    const int wn  = wid >> 1;           // 0..3
    const int m0  = blockIdx.y * 128;
    const int n0  = blockIdx.x * 128;

    const int ldr = tid >> 3;           // 0..31 -> row pair base
    const int ldc = (tid & 7) << 2;     // 0,4,..,28

    float acc[4][4][4] = {};            // [mfrag][nfrag][4]

    const int NS = K >> 5;

    // ---- load slab 0 into buffer 0 ----
    {
        const float* Ap = A  + (size_t)m0 * K;
        const float* Bp = BT + (size_t)n0 * K;
#pragma unroll
        for (int i = 0; i < 4; i++) {
            int r = ldr + (i << 5);     // 0..127
            uint32_t idx = r * 32 + (ldc ^ ((r & 7) << 2));
            float4 va = *(const float4*)(Ap + (size_t)r * K + ldc);
            float4 vb = *(const float4*)(Bp + (size_t)r * K + ldc);
            uint4 ta = make_uint4(f2tf32(va.x), f2tf32(va.y), f2tf32(va.z), f2tf32(va.w));
            uint4 tb = make_uint4(f2tf32(vb.x), f2tf32(vb.y), f2tf32(vb.z), f2tf32(vb.w));
            *(uint4*)&Asm[idx] = ta;
            *(uint4*)&Bsm[idx] = tb;
        }
    }
    __syncthreads();

    for (int s = 0; s < NS; s++) {
        const int cur = s & 1;
        const int nxt = cur ^ 1;
        const uint32_t* Ab = Asm + cur * 4096;
        const uint32_t* Bb = Bsm + cur * 4096;

        // prefetch next slab into registers
        float4 ra[4], rb[4];
        if (s + 1 < NS) {
            const float* Ap = A  + (size_t)m0 * K + (s + 1) * 32;
            const float* Bp = BT + (size_t)n0 * K + (s + 1) * 32;
#pragma unroll
            for (int i = 0; i < 4; i++) {
                int r = ldr + (i << 5);
                ra[i] = *(const float4*)(Ap + (size_t)r * K + ldc);
                rb[i] = *(const float4*)(Bp + (size_t)r * K + ldc);
            }
        }

        // compute 4 k8-steps on cur
#pragma unroll
        for (int kc = 0; kc < 32; kc += 8) {
            uint32_t a[4][4], b[4][2];
#pragma unroll
            for (int i = 0; i < 4; i++) {
                const uint32_t* p0 = Ab + (wm * 64 + i * 16 + lr) * 32;
                const uint32_t* p8 = p0 + 8 * 32;
                a[i][0] = p0[(kc + la)     ^ sx];
                a[i][1] = p8[(kc + la)     ^ sx];
                a[i][2] = p0[(kc + la + 4) ^ sx];
                a[i][3] = p8[(kc + la + 4) ^ sx];
            }
#pragma unroll
            for (int j = 0; j < 4; j++) {
                const uint32_t* pb = Bb + (wn * 32 + j * 8 + lr) * 32;
                b[j][0] = pb[(kc + la)     ^ sx];
                b[j][1] = pb[(kc + la + 4) ^ sx];
            }
#pragma unroll
            for (int i = 0; i < 4; i++)
#pragma unroll
                for (int j = 0; j < 4; j++)
                    MMA_TF32(acc[i][j][0], acc[i][j][1], acc[i][j][2], acc[i][j][3],
                             a[i][0], a[i][1], a[i][2], a[i][3], b[j][0], b[j][1]);
        }

        if (s + 1 < NS) {
            uint32_t* An = Asm + nxt * 4096;
            uint32_t* Bn = Bsm + nxt * 4096;
#pragma unroll
            for (int i = 0; i < 4; i++) {
                int r = ldr + (i << 5);
                uint32_t idx = r * 32 + (ldc ^ ((r & 7) << 2));
                *(uint4*)&An[idx] = make_uint4(f2tf32(ra[i].x), f2tf32(ra[i].y),
                                               f2tf32(ra[i].z), f2tf32(ra[i].w));
                *(uint4*)&Bn[idx] = make_uint4(f2tf32(rb[i].x), f2tf32(rb[i].y),
                                               f2tf32(rb[i].z), f2tf32(rb[i].w));
            }
            __syncthreads();
        }
    }

    // ---- epilogue: direct global writes, float2 per (frag, half) ----
#pragma unroll
    for (int i = 0; i < 4; i++) {
        int mlo = m0 + wm * 64 + i * 16 + lr;
#pragma unroll
        for (int j = 0; j < 4; j++) {
            int n = n0 + wn * 32 + j * 8 + la * 2;
            float2 bz = *(const float2*)(bias + n);
            float2 v0 = make_float2(acc[i][j][0] + bz.x, acc[i][j][1] + bz.y);
            float2 v1 = make_float2(acc[i][j][2] + bz.x, acc[i][j][3] + bz.y);
            if (RES) {
                float2 r0 = *(const float2*)(R + (size_t)mlo * N + n);
                float2 r1 = *(const float2*)(R + (size_t)(mlo + 8) * N + n);
                v0.x += r0.x; v0.y += r0.y; v1.x += r1.x; v1.y += r1.y;
            }
            if (RELU) {
                v0.x = fmaxf(v0.x, 0.f); v0.y = fmaxf(v0.y, 0.f);
                v1.x = fmaxf(v1.x, 0.f); v1.y = fmaxf(v1.y, 0.f);
            }
            *(float2*)(C + (size_t)mlo * N + n) = v0;
            *(float2*)(C + (size_t)(mlo + 8) * N + n) = v1;
        }
    }
}

// =====================================================================
// Flash attention (fp32), vectorized smem access. CTA = (b, h, 64 q-rows).
// =====================================================================
#define ALD 68
#define ATTN_SMEM_BYTES ((4*64*ALD + 3*64) * 4)

__global__ void __launch_bounds__(256) attn_kernel(
    const float* __restrict__ Q, const float* __restrict__ K,
    const float* __restrict__ V, float* __restrict__ O)
{
    const int s0 = blockIdx.x * 64;
    const int h  = blockIdx.y;
    const int b  = blockIdx.z;

    extern __shared__ float smf[];
    float* Qs = smf;
    float* Ks = Qs + 64 * ALD;
    float* Vs = Ks + 64 * ALD;
    float* Ps = Vs + 64 * ALD;
    float* rm = Ps + 64 * ALD;
    float* rl = rm + 64;
    float* rc = rl + 64;

    const int tid = threadIdx.x;
    const int tx  = tid & 15;
    const int ty  = tid >> 4;
    const size_t base = (size_t)b * SEQ * DM + (size_t)h * DH;

    {
        int r = tid >> 4, c = (tid & 15) << 2;
#pragma unroll
        for (int p = 0; p < 4; p++) {
            int row = r + p * 16;
            *(float4*)(Qs + row * ALD + c) =
                *(const float4*)(Q + base + (size_t)(s0 + row) * DM + c);
        }
    }
    if (tid < 64) { rm[tid] = -1e30f; rl[tid] = 0.f; }

    float o[4][4] = {};

    for (int j0 = 0; j0 < SEQ; j0 += 64) {
        __syncthreads();
        {
            int r = tid >> 4, c = (tid & 15) << 2;
#pragma unroll
            for (int p = 0; p < 4; p++) {
                int row = r + p * 16;
                *(float4*)(Ks + row * ALD + c) =
                    *(const float4*)(K + base + (size_t)(j0 + row) * DM + c);
                *(float4*)(Vs + row * ALD + c) =
                    *(const float4*)(V + base + (size_t)(j0 + row) * DM + c);
            }
        }
        __syncthreads();

        // S = Q K^T * scale
        float s[4][4] = {};
#pragma unroll 4
        for (int k4 = 0; k4 < 16; k4++) {
            float4 q0 = *(const float4*)(Qs + (ty * 4 + 0) * ALD + k4 * 4);
            float4 q1 = *(const float4*)(Qs + (ty * 4 + 1) * ALD + k4 * 4);
            float4 q2 = *(const float4*)(Qs + (ty * 4 + 2) * ALD + k4 * 4);
            float4 q3 = *(const float4*)(Qs + (ty * 4 + 3) * ALD + k4 * 4);
#pragma unroll
            for (int jj = 0; jj < 4; jj++) {
                float4 kb = *(const float4*)(Ks + (tx + 16 * jj) * ALD + k4 * 4);
                s[0][jj] += q0.x * kb.x + q0.y * kb.y + q0.z * kb.z + q0.w * kb.w;
                s[1][jj] += q1.x * kb.x + q1.y * kb.y + q1.z * kb.z + q1.w * kb.w;
                s[2][jj] += q2.x * kb.x + q2.y * kb.y + q2.z * kb.z + q2.w * kb.w;
                s[3][jj] += q3.x * kb.x + q3.y * kb.y + q3.z * kb.z + q3.w * kb.w;
            }
        }
#pragma unroll
        for (int ii = 0; ii < 4; ii++)
#pragma unroll
            for (int jj = 0; jj < 4; jj++)
                Ps[(ty * 4 + ii) * ALD + tx + 16 * jj] = s[ii][jj] * 0.125f;
        __syncthreads();

        // online softmax: 4 threads per row, 16 elements each
        {
            int r  = tid >> 2;
            int qo = (tid & 3) << 4;
            float m_old = rm[r];
            float4 p0 = *(const float4*)(Ps + r * ALD + qo + 0);
            float4 p1 = *(const float4*)(Ps + r * ALD + qo + 4);
            float4 p2 = *(const float4*)(Ps + r * ALD + qo + 8);
            float4 p3 = *(const float4*)(Ps + r * ALD + qo + 12);
            float mx = m_old;
            mx = fmaxf(mx, fmaxf(fmaxf(p0.x, p0.y), fmaxf(p0.z, p0.w)));
            mx = fmaxf(mx, fmaxf(fmaxf(p1.x, p1.y), fmaxf(p1.z, p1.w)));
            mx = fmaxf(mx, fmaxf(fmaxf(p2.x, p2.y), fmaxf(p2.z, p2.w)));
            mx = fmaxf(mx, fmaxf(fmaxf(p3.x, p3.y), fmaxf(p3.z, p3.w)));
            mx = fmaxf(mx, __shfl_xor_sync(0xFFFFFFFFu, mx, 1));
            mx = fmaxf(mx, __shfl_xor_sync(0xFFFFFFFFu, mx, 2));
            float lsum = 0.f;
            p0.x = __expf(p0.x - mx); lsum += p0.x;  p0.y = __expf(p0.y - mx); lsum += p0.y;
            p0.z = __expf(p0.z - mx); lsum += p0.z;  p0.w = __expf(p0.w - mx); lsum += p0.w;
            p1.x = __expf(p1.x - mx); lsum += p1.x;  p1.y = __expf(p1.y - mx); lsum += p1.y;
            p1.z = __expf(p1.z - mx); lsum += p1.z;  p1.w = __expf(p1.w - mx); lsum += p1.w;
            p2.x = __expf(p2.x - mx); lsum += p2.x;  p2.y = __expf(p2.y - mx); lsum += p2.y;
            p2.z = __expf(p2.z - mx); lsum += p2.z;  p2.w = __expf(p2.w - mx); lsum += p2.w;
            p3.x = __expf(p3.x - mx); lsum += p3.x;  p3.y = __expf(p3.y - mx); lsum += p3.y;
            p3.z = __expf(p3.z - mx); lsum += p3.z;  p3.w = __expf(p3.w - mx); lsum += p3.w;
            *(float4*)(Ps + r * ALD + qo + 0)  = p0;
            *(float4*)(Ps + r * ALD + qo + 4)  = p1;
            *(float4*)(Ps + r * ALD + qo + 8)  = p2;
            *(float4*)(Ps + r * ALD + qo + 12) = p3;
            lsum += __shfl_xor_sync(0xFFFFFFFFu, lsum, 1);
            lsum += __shfl_xor_sync(0xFFFFFFFFu, lsum, 2);
            if ((tid & 3) == 0) {
                float cf = __expf(m_old - mx);
                rm[r] = mx; rl[r] = rl[r] * cf + lsum; rc[r] = cf;
            }
        }
        __syncthreads();

        // O = O*cf + P @ V
        float c0 = rc[ty * 4 + 0], c1 = rc[ty * 4 + 1];
        float c2 = rc[ty * 4 + 2], c3 = rc[ty * 4 + 3];
#pragma unroll
        for (int jj = 0; jj < 4; jj++) {
            o[0][jj] *= c0; o[1][jj] *= c1; o[2][jj] *= c2; o[3][jj] *= c3;
        }
#pragma unroll 4
        for (int j4 = 0; j4 < 16; j4++) {
            float4 a0 = *(const float4*)(Ps + (ty * 4 + 0) * ALD + j4 * 4);
            float4 a1 = *(const float4*)(Ps + (ty * 4 + 1) * ALD + j4 * 4);
            float4 a2 = *(const float4*)(Ps + (ty * 4 + 2) * ALD + j4 * 4);
            float4 a3 = *(const float4*)(Ps + (ty * 4 + 3) * ALD + j4 * 4);
            float a0v[4] = {a0.x, a0.y, a0.z, a0.w};
            float a1v[4] = {a1.x, a1.y, a1.z, a1.w};
            float a2v[4] = {a2.x, a2.y, a2.z, a2.w};
            float a3v[4] = {a3.x, a3.y, a3.z, a3.w};
#pragma unroll
            for (int jj = 0; jj < 4; jj++) {
                float4 vr = *(const float4*)(Vs + (j4 * 4 + jj) * ALD + (tx << 2));
                o[0][0] += a0v[jj] * vr.x; o[0][1] += a0v[jj] * vr.y;
                o[0][2] += a0v[jj] * vr.z; o[0][3] += a0v[jj] * vr.w;
                o[1][0] += a1v[jj] * vr.x; o[1][1] += a1v[jj] * vr.y;
                o[1][2] += a1v[jj] * vr.z; o[1][3] += a1v[jj] * vr.w;
                o[2][0] += a2v[jj] * vr.x; o[2][1] += a2v[jj] * vr.y;
                o[2][2] += a2v[jj] * vr.z; o[2][3] += a2v[jj] * vr.w;
                o[3][0] += a3v[jj] * vr.x; o[3][1] += a3v[jj] * vr.y;
                o[3][2] += a3v[jj] * vr.z; o[3][3] += a3v[jj] * vr.w;
            }
        }
    }
    __syncthreads();

#pragma unroll
    for (int ii = 0; ii < 4; ii++) {
        float inv = 1.f / rl[ty * 4 + ii];
        float4 v = make_float4(o[ii][0] * inv, o[ii][1] * inv, o[ii][2] * inv, o[ii][3] * inv);
        *(float4*)(O + base + (size_t)(s0 + ty * 4 + ii) * DM + (tx << 2)) = v;
    }
}

// =====================================================================
// LayerNorm over 512-element rows.
// =====================================================================
__global__ void __launch_bounds__(128) ln_kernel(
    const float* __restrict__ X, const float* __restrict__ g,
    const float* __restrict__ be, float* __restrict__ Y)
{
    const int row = blockIdx.x;
    const int tid = threadIdx.x;
    const float* x = X + (size_t)row * DM;

    float4 v = *(const float4*)(x + (tid << 2));
    float s = v.x + v.y + v.z + v.w;
    float q = v.x * v.x + v.y * v.y + v.z * v.z + v.w * v.w;
#pragma unroll
    for (int o = 16; o; o >>= 1) {
        s += __shfl_xor_sync(0xFFFFFFFFu, s, o);
        q += __shfl_xor_sync(0xFFFFFFFFu, q, o);
    }
    __shared__ float ss[4], qq[4];
    if ((tid & 31) == 0) { ss[tid >> 5] = s; qq[tid >> 5] = q; }
    __syncthreads();
    s = ss[0] + ss[1] + ss[2] + ss[3];
    q = qq[0] + qq[1] + qq[2] + qq[3];
    float mean = s * (1.f / DM);
    float var  = q * (1.f / DM) - mean * mean;
    float rstd = rsqrtf(var + 1e-5f);

    float4 gv = *(const float4*)(g  + (tid << 2));
    float4 bv = *(const float4*)(be + (tid << 2));
    float4 y;
    y.x = (v.x - mean) * rstd * gv.x + bv.x;
    y.y = (v.y - mean) * rstd * gv.y + bv.y;
    y.z = (v.z - mean) * rstd * gv.z + bv.z;
    y.w = (v.w - mean) * rstd * gv.w + bv.w;
    *(float4*)(Y + (size_t)row * DM + (tid << 2)) = y;
}

// =====================================================================
extern "C" void kernel_launch(void* const* d_in, const int* in_sizes, int n_in,
                              void* d_out, int out_size)
{
    const float* z_in = (const float*)d_in[0];
    const float* Wq = (const float*)d_in[1];
    const float* bq = (const float*)d_in[2];
    const float* Wk = (const float*)d_in[3];
    const float* bk = (const float*)d_in[4];
    const float* Wv = (const float*)d_in[5];
    const float* bv = (const float*)d_in[6];
    const float* Wo = (const float*)d_in[7];
    const float* bo = (const float*)d_in[8];
    const float* W1 = (const float*)d_in[9];
    const float* b1 = (const float*)d_in[10];
    const float* W2 = (const float*)d_in[11];
    const float* b2 = (const float*)d_in[12];
    const float* g1 = (const float*)d_in[13];
    const float* be1 = (const float*)d_in[14];
    const float* g2 = (const float*)d_in[15];
    const float* be2 = (const float*)d_in[16];
    float* out = (float*)d_out;

    float *Qb, *Kb, *Vb, *Ob, *Tb, *Zb, *H1b;
    float *WqTb, *WkTb, *WvTb, *WoTb, *W1Tb, *W2Tb;
    cudaGetSymbolAddress((void**)&Qb, g_Q);
    cudaGetSymbolAddress((void**)&Kb, g_K);
    cudaGetSymbolAddress((void**)&Vb, g_V);
    cudaGetSymbolAddress((void**)&Ob, g_O);
    cudaGetSymbolAddress((void**)&Tb, g_T);
    cudaGetSymbolAddress((void**)&Zb, g_Z);
    cudaGetSymbolAddress((void**)&H1b, g_H1);
    cudaGetSymbolAddress((void**)&WqTb, g_WqT);
    cudaGetSymbolAddress((void**)&WkTb, g_WkT);
    cudaGetSymbolAddress((void**)&WvTb, g_WvT);
    cudaGetSymbolAddress((void**)&WoTb, g_WoT);
    cudaGetSymbolAddress((void**)&W1Tb, g_W1T);
    cudaGetSymbolAddress((void**)&W2Tb, g_W2T);

    cudaFuncSetAttribute(attn_kernel,
        cudaFuncAttributeMaxDynamicSharedMemorySize, ATTN_SMEM_BYTES);
    cudaFuncSetAttribute(mma_gemm<false, false>,
        cudaFuncAttributeMaxDynamicSharedMemorySize, G_SMEM_BYTES);
    cudaFuncSetAttribute(mma_gemm<false, true>,
        cudaFuncAttributeMaxDynamicSharedMemorySize, G_SMEM_BYTES);
    cudaFuncSetAttribute(mma_gemm<true, false>,
        cudaFuncAttributeMaxDynamicSharedMemorySize, G_SMEM_BYTES);

    // weight pre-transposes
    headed_T_kernel<<<(DM * DM) / 256, 256>>>(Wq, WqTb);
    headed_T_kernel<<<(DM * DM) / 256, 256>>>(Wk, WkTb);
    headed_T_kernel<<<(DM * DM) / 256, 256>>>(Wv, WvTb);
    matT_kernel<<<(DM * DM + 255) / 256, 256>>>(Wo, WoTb, DM, DM);
    matT_kernel<<<(DM * DFF + 255) / 256, 256>>>(W1, W1Tb, DM, DFF);
    matT_kernel<<<(DFF * DM + 255) / 256, 256>>>(W2, W2Tb, DFF, DM);

    dim3 blk(256);
    dim3 gP (DM  / 128, ROWS / 128);   // (4, 32)
    dim3 gF1(DFF / 128, ROWS / 128);   // (16, 32)
    dim3 gAttn(SEQ / 64, NH, BB);

    for (int it = 0; it < 4; it++) {
        const float* z = (it == 0) ? z_in : Zb;

        mma_gemm<false, false><<<gP, blk, G_SMEM_BYTES>>>(z, WqTb, bq, nullptr, Qb, ROWS, DM, DM);
        mma_gemm<false, false><<<gP, blk, G_SMEM_BYTES>>>(z, WkTb, bk, nullptr, Kb, ROWS, DM, DM);
        mma_gemm<false, false><<<gP, blk, G_SMEM_BYTES>>>(z, WvTb, bv, nullptr, Vb, ROWS, DM, DM);

        attn_kernel<<<gAttn, blk, ATTN_SMEM_BYTES>>>(Qb, Kb, Vb, Ob);

        mma_gemm<false, true><<<gP, blk, G_SMEM_BYTES>>>(Ob, WoTb, bo, z, Tb, ROWS, DM, DM);

        float* lnout = (it == 3) ? out : Zb;
        ln_kernel<<<ROWS, 128>>>(Tb, g1, be1, lnout);

        if (it < 3) {
            mma_gemm<true, false><<<gF1, blk, G_SMEM_BYTES>>>(Zb, W1Tb, b1, nullptr, H1b, ROWS, DFF, DM);
            mma_gemm<false, true><<<gP, blk, G_SMEM_BYTES>>>(H1b, W2Tb, b2, Zb, Tb, ROWS, DM, DFF);
            ln_kernel<<<ROWS, 128>>>(Tb, g2, be2, Zb);
        }
    }
}

// round 4
// speedup vs baseline: 3.1102x; 1.8188x over previous
#include <cuda_runtime.h>
#include <cstdint>
#include <math.h>

#define DM   512
#define DFF  2048
#define NH   8
#define DH   64
#define BB   2
#define SEQ  2048
#define ROWS (BB*SEQ)   // 4096

// ---------------- static scratch (no allocations allowed) ----------------
__device__ float g_Q  [ROWS*DM];
__device__ float g_K  [ROWS*DM];
__device__ float g_V  [ROWS*DM];
__device__ float g_O  [ROWS*DM];
__device__ float g_T  [ROWS*DM];
__device__ float g_Z  [ROWS*DM];
__device__ float g_H1 [ROWS*DFF];
__device__ float g_WqT[DM*DM];
__device__ float g_WkT[DM*DM];
__device__ float g_WvT[DM*DM];
__device__ float g_WoT[DM*DM];
__device__ float g_W1T[DFF*DM];
__device__ float g_W2T[DM*DFF];

__device__ __forceinline__ uint32_t f2tf32(float f) {
    uint32_t r;
    asm("cvt.rna.tf32.f32 %0, %1;" : "=r"(r) : "f"(f));
    return r;
}

#define MMA_TF32(d0,d1,d2,d3, a0,a1,a2,a3, b0,b1) \
    asm volatile("mma.sync.aligned.m16n8k8.row.col.f32.tf32.tf32.f32 " \
        "{%0,%1,%2,%3}, {%4,%5,%6,%7}, {%8,%9}, {%0,%1,%2,%3};" \
        : "+f"(d0), "+f"(d1), "+f"(d2), "+f"(d3) \
        : "r"(a0), "r"(a1), "r"(a2), "r"(a3), "r"(b0), "r"(b1))

// =====================================================================
// Weight pre-transpose kernels (run once per call)
// =====================================================================
__global__ void headed_T_kernel(const float* __restrict__ W, float* __restrict__ out) {
    int idx = blockIdx.x * 256 + threadIdx.x;            // over 512*512
    int n = idx >> 9, k = idx & 511;
    out[idx] = W[(size_t)(n >> 6) * (512 * 64) + (size_t)k * 64 + (n & 63)];
}
__global__ void matT_kernel(const float* __restrict__ in, float* __restrict__ out, int R, int C) {
    int idx = blockIdx.x * 256 + threadIdx.x;
    if (idx >= R * C) return;
    int c = idx / R, r = idx - c * R;
    out[idx] = in[(size_t)r * C + c];
}

// =====================================================================
// TF32 mma.sync GEMM (unchanged from round 3; proven)
// =====================================================================
#define G_SMEM_BYTES (2 * 2 * 128 * 32 * 4)   // 65536

template<bool RELU, bool RES>
__global__ void __launch_bounds__(256) mma_gemm(
    const float* __restrict__ A, const float* __restrict__ BT,
    const float* __restrict__ bias, const float* __restrict__ R,
    float* __restrict__ C, int M, int N, int K)
{
    extern __shared__ uint32_t sm[];
    uint32_t* Asm = sm;                 // [2][4096]
    uint32_t* Bsm = sm + 8192;          // [2][4096]

    const int tid = threadIdx.x;
    const int wid = tid >> 5, l = tid & 31;
    const int lr  = l >> 2, la = l & 3;
    const int sx  = lr << 2;
    const int wm  = wid & 1;
    const int wn  = wid >> 1;
    const int m0  = blockIdx.y * 128;
    const int n0  = blockIdx.x * 128;

    const int ldr = tid >> 3;
    const int ldc = (tid & 7) << 2;

    float acc[4][4][4] = {};
    const int NS = K >> 5;

    {
        const float* Ap = A  + (size_t)m0 * K;
        const float* Bp = BT + (size_t)n0 * K;
#pragma unroll
        for (int i = 0; i < 4; i++) {
            int r = ldr + (i << 5);
            uint32_t idx = r * 32 + (ldc ^ ((r & 7) << 2));
            float4 va = *(const float4*)(Ap + (size_t)r * K + ldc);
            float4 vb = *(const float4*)(Bp + (size_t)r * K + ldc);
            *(uint4*)&Asm[idx] = make_uint4(f2tf32(va.x), f2tf32(va.y), f2tf32(va.z), f2tf32(va.w));
            *(uint4*)&Bsm[idx] = make_uint4(f2tf32(vb.x), f2tf32(vb.y), f2tf32(vb.z), f2tf32(vb.w));
        }
    }
    __syncthreads();

    for (int s = 0; s < NS; s++) {
        const int cur = s & 1;
        const int nxt = cur ^ 1;
        const uint32_t* Ab = Asm + cur * 4096;
        const uint32_t* Bb = Bsm + cur * 4096;

        float4 ra[4], rb[4];
        if (s + 1 < NS) {
            const float* Ap = A  + (size_t)m0 * K + (s + 1) * 32;
            const float* Bp = BT + (size_t)n0 * K + (s + 1) * 32;
#pragma unroll
            for (int i = 0; i < 4; i++) {
                int r = ldr + (i << 5);
                ra[i] = *(const float4*)(Ap + (size_t)r * K + ldc);
                rb[i] = *(const float4*)(Bp + (size_t)r * K + ldc);
            }
        }

#pragma unroll
        for (int kc = 0; kc < 32; kc += 8) {
            uint32_t a[4][4], b[4][2];
#pragma unroll
            for (int i = 0; i < 4; i++) {
                const uint32_t* p0 = Ab + (wm * 64 + i * 16 + lr) * 32;
                const uint32_t* p8 = p0 + 8 * 32;
                a[i][0] = p0[(kc + la)     ^ sx];
                a[i][1] = p8[(kc + la)     ^ sx];
                a[i][2] = p0[(kc + la + 4) ^ sx];
                a[i][3] = p8[(kc + la + 4) ^ sx];
            }
#pragma unroll
            for (int j = 0; j < 4; j++) {
                const uint32_t* pb = Bb + (wn * 32 + j * 8 + lr) * 32;
                b[j][0] = pb[(kc + la)     ^ sx];
                b[j][1] = pb[(kc + la + 4) ^ sx];
            }
#pragma unroll
            for (int i = 0; i < 4; i++)
#pragma unroll
                for (int j = 0; j < 4; j++)
                    MMA_TF32(acc[i][j][0], acc[i][j][1], acc[i][j][2], acc[i][j][3],
                             a[i][0], a[i][1], a[i][2], a[i][3], b[j][0], b[j][1]);
        }

        if (s + 1 < NS) {
            uint32_t* An = Asm + nxt * 4096;
            uint32_t* Bn = Bsm + nxt * 4096;
#pragma unroll
            for (int i = 0; i < 4; i++) {
                int r = ldr + (i << 5);
                uint32_t idx = r * 32 + (ldc ^ ((r & 7) << 2));
                *(uint4*)&An[idx] = make_uint4(f2tf32(ra[i].x), f2tf32(ra[i].y),
                                               f2tf32(ra[i].z), f2tf32(ra[i].w));
                *(uint4*)&Bn[idx] = make_uint4(f2tf32(rb[i].x), f2tf32(rb[i].y),
                                               f2tf32(rb[i].z), f2tf32(rb[i].w));
            }
            __syncthreads();
        }
    }

#pragma unroll
    for (int i = 0; i < 4; i++) {
        int mlo = m0 + wm * 64 + i * 16 + lr;
#pragma unroll
        for (int j = 0; j < 4; j++) {
            int n = n0 + wn * 32 + j * 8 + la * 2;
            float2 bz = *(const float2*)(bias + n);
            float2 v0 = make_float2(acc[i][j][0] + bz.x, acc[i][j][1] + bz.y);
            float2 v1 = make_float2(acc[i][j][2] + bz.x, acc[i][j][3] + bz.y);
            if (RES) {
                float2 r0 = *(const float2*)(R + (size_t)mlo * N + n);
                float2 r1 = *(const float2*)(R + (size_t)(mlo + 8) * N + n);
                v0.x += r0.x; v0.y += r0.y; v1.x += r1.x; v1.y += r1.y;
            }
            if (RELU) {
                v0.x = fmaxf(v0.x, 0.f); v0.y = fmaxf(v0.y, 0.f);
                v1.x = fmaxf(v1.x, 0.f); v1.y = fmaxf(v1.y, 0.f);
            }
            *(float2*)(C + (size_t)mlo * N + n) = v0;
            *(float2*)(C + (size_t)(mlo + 8) * N + n) = v1;
        }
    }
}

// =====================================================================
// Flash attention with mma.sync tf32.
// CTA = 128 q-rows x one (b,h). 8 warps, warp w owns rows [w*16, w*16+16).
// Q pre-scaled by 0.125 (exact), held in registers as a-fragments.
// Key tiles of 64. K/V in smem (tf32, pad-68 rows). P restaged into the
// Q buffer (per-warp disjoint rows -> __syncwarp only).
// =====================================================================
#define APAD 68
#define A_QP 0
#define A_K  (128*APAD)
#define A_V  (128*APAD + 64*APAD)
#define ATTN_SMEM_BYTES ((128*APAD + 64*APAD + 64*APAD) * 4)   // 69632

__global__ void __launch_bounds__(256, 2) attn_mma(
    const float* __restrict__ Q, const float* __restrict__ K,
    const float* __restrict__ V, float* __restrict__ O)
{
    extern __shared__ uint32_t as[];
    uint32_t* QP = as + A_QP;
    uint32_t* Ks = as + A_K;
    uint32_t* Vs = as + A_V;

    const int tid = threadIdx.x;
    const int wid = tid >> 5, l = tid & 31;
    const int lr = l >> 2, la = l & 3;
    const int q0 = blockIdx.x * 128;
    const int h  = blockIdx.y, b = blockIdx.z;
    const size_t base = (size_t)b * SEQ * DM + (size_t)h * DH;

    // ---- stage Q (scaled by 1/8) ----
    {
        int r = tid >> 1, c0 = (tid & 1) * 32;
        const float* src = Q + base + (size_t)(q0 + r) * DM + c0;
        uint32_t* dst = QP + r * APAD + c0;
#pragma unroll
        for (int i = 0; i < 8; i++) {
            float4 v = *(const float4*)(src + i * 4);
            dst[i*4+0] = f2tf32(v.x * 0.125f);
            dst[i*4+1] = f2tf32(v.y * 0.125f);
            dst[i*4+2] = f2tf32(v.z * 0.125f);
            dst[i*4+3] = f2tf32(v.w * 0.125f);
        }
    }
    __syncthreads();

    // ---- Q a-fragments into registers ----
    uint32_t aq[8][4];
    {
        const uint32_t* q0p = QP + (wid * 16 + lr) * APAD;
        const uint32_t* q8p = q0p + 8 * APAD;
#pragma unroll
        for (int k = 0; k < 8; k++) {
            aq[k][0] = q0p[k*8 + la];
            aq[k][1] = q8p[k*8 + la];
            aq[k][2] = q0p[k*8 + la + 4];
            aq[k][3] = q8p[k*8 + la + 4];
        }
    }
    // QP rows [wid*16, wid*16+16) now owned by this warp for P staging.

    float o[8][4] = {};
    float m_lo = -1e30f, m_hi = -1e30f, l_lo = 0.f, l_hi = 0.f;

    for (int j0 = 0; j0 < SEQ; j0 += 64) {
        __syncthreads();   // previous tile's V reads done
        // ---- stage K, V tile (64x64) ----
        {
            int r = tid >> 2, cb = (tid & 3) << 2;
            const float* ksrc = K + base + (size_t)(j0 + r) * DM;
            const float* vsrc = V + base + (size_t)(j0 + r) * DM;
            uint32_t* kd = Ks + r * APAD;
            uint32_t* vd = Vs + r * APAD;
#pragma unroll
            for (int i = 0; i < 4; i++) {
                int c = cb + i * 16;
                float4 kv = *(const float4*)(ksrc + c);
                float4 vv = *(const float4*)(vsrc + c);
                kd[c+0] = f2tf32(kv.x); kd[c+1] = f2tf32(kv.y);
                kd[c+2] = f2tf32(kv.z); kd[c+3] = f2tf32(kv.w);
                vd[c+0] = f2tf32(vv.x); vd[c+1] = f2tf32(vv.y);
                vd[c+2] = f2tf32(vv.z); vd[c+3] = f2tf32(vv.w);
            }
        }
        __syncthreads();

        // ---- S = Q K^T (scaled) ----
        float s[8][4] = {};
#pragma unroll
        for (int k = 0; k < 8; k++) {
#pragma unroll
            for (int j = 0; j < 8; j++) {
                const uint32_t* kb = Ks + (j*8 + lr) * APAD + k*8;
                uint32_t b0 = kb[la], b1 = kb[la + 4];
                MMA_TF32(s[j][0], s[j][1], s[j][2], s[j][3],
                         aq[k][0], aq[k][1], aq[k][2], aq[k][3], b0, b1);
            }
        }

        // ---- online softmax (rows lr and lr+8) ----
        float tml = -1e30f, tmh = -1e30f;
#pragma unroll
        for (int j = 0; j < 8; j++) {
            tml = fmaxf(tml, fmaxf(s[j][0], s[j][1]));
            tmh = fmaxf(tmh, fmaxf(s[j][2], s[j][3]));
        }
        tml = fmaxf(tml, __shfl_xor_sync(0xFFFFFFFFu, tml, 1));
        tml = fmaxf(tml, __shfl_xor_sync(0xFFFFFFFFu, tml, 2));
        tmh = fmaxf(tmh, __shfl_xor_sync(0xFFFFFFFFu, tmh, 1));
        tmh = fmaxf(tmh, __shfl_xor_sync(0xFFFFFFFFu, tmh, 2));
        float mnl = fmaxf(m_lo, tml), mnh = fmaxf(m_hi, tmh);
        float cfl = __expf(m_lo - mnl), cfh = __expf(m_hi - mnh);
        m_lo = mnl; m_hi = mnh;

        float suml = 0.f, sumh = 0.f;
#pragma unroll
        for (int j = 0; j < 8; j++) {
            s[j][0] = __expf(s[j][0] - mnl); suml += s[j][0];
            s[j][1] = __expf(s[j][1] - mnl); suml += s[j][1];
            s[j][2] = __expf(s[j][2] - mnh); sumh += s[j][2];
            s[j][3] = __expf(s[j][3] - mnh); sumh += s[j][3];
        }
        suml += __shfl_xor_sync(0xFFFFFFFFu, suml, 1);
        suml += __shfl_xor_sync(0xFFFFFFFFu, suml, 2);
        sumh += __shfl_xor_sync(0xFFFFFFFFu, sumh, 1);
        sumh += __shfl_xor_sync(0xFFFFFFFFu, sumh, 2);
        l_lo = l_lo * cfl + suml;
        l_hi = l_hi * cfh + sumh;

#pragma unroll
        for (int j = 0; j < 8; j++) {
            o[j][0] *= cfl; o[j][1] *= cfl;
            o[j][2] *= cfh; o[j][3] *= cfh;
        }

        // ---- stage P into warp-owned rows of QP ----
        uint32_t* p0w = QP + (wid * 16 + lr) * APAD;
        uint32_t* p8w = p0w + 8 * APAD;
#pragma unroll
        for (int j = 0; j < 8; j++) {
            p0w[j*8 + 2*la]     = f2tf32(s[j][0]);
            p0w[j*8 + 2*la + 1] = f2tf32(s[j][1]);
            p8w[j*8 + 2*la]     = f2tf32(s[j][2]);
            p8w[j*8 + 2*la + 1] = f2tf32(s[j][3]);
        }
        __syncwarp();

        // ---- O += P @ V ----
#pragma unroll
        for (int k = 0; k < 8; k++) {
            uint32_t ap0 = p0w[k*8 + la];
            uint32_t ap1 = p8w[k*8 + la];
            uint32_t ap2 = p0w[k*8 + la + 4];
            uint32_t ap3 = p8w[k*8 + la + 4];
#pragma unroll
            for (int j = 0; j < 8; j++) {
                uint32_t b0 = Vs[(k*8 + la) * APAD + j*8 + lr];
                uint32_t b1 = Vs[(k*8 + la + 4) * APAD + j*8 + lr];
                MMA_TF32(o[j][0], o[j][1], o[j][2], o[j][3],
                         ap0, ap1, ap2, ap3, b0, b1);
            }
        }
    }

    // ---- epilogue ----
    float invl = 1.f / l_lo, invh = 1.f / l_hi;
    float* d0 = O + base + (size_t)(q0 + wid * 16 + lr) * DM;
    float* d8 = d0 + 8 * DM;
#pragma unroll
    for (int j = 0; j < 8; j++) {
        *(float2*)(d0 + j*8 + 2*la) = make_float2(o[j][0] * invl, o[j][1] * invl);
        *(float2*)(d8 + j*8 + 2*la) = make_float2(o[j][2] * invh, o[j][3] * invh);
    }
}

// =====================================================================
// LayerNorm over 512-element rows.
// =====================================================================
__global__ void __launch_bounds__(128) ln_kernel(
    const float* __restrict__ X, const float* __restrict__ g,
    const float* __restrict__ be, float* __restrict__ Y)
{
    const int row = blockIdx.x;
    const int tid = threadIdx.x;
    const float* x = X + (size_t)row * DM;

    float4 v = *(const float4*)(x + (tid << 2));
    float s = v.x + v.y + v.z + v.w;
    float q = v.x * v.x + v.y * v.y + v.z * v.z + v.w * v.w;
#pragma unroll
    for (int o = 16; o; o >>= 1) {
        s += __shfl_xor_sync(0xFFFFFFFFu, s, o);
        q += __shfl_xor_sync(0xFFFFFFFFu, q, o);
    }
    __shared__ float ss[4], qq[4];
    if ((tid & 31) == 0) { ss[tid >> 5] = s; qq[tid >> 5] = q; }
    __syncthreads();
    s = ss[0] + ss[1] + ss[2] + ss[3];
    q = qq[0] + qq[1] + qq[2] + qq[3];
    float mean = s * (1.f / DM);
    float var  = q * (1.f / DM) - mean * mean;
    float rstd = rsqrtf(var + 1e-5f);

    float4 gv = *(const float4*)(g  + (tid << 2));
    float4 bv = *(const float4*)(be + (tid << 2));
    float4 y;
    y.x = (v.x - mean) * rstd * gv.x + bv.x;
    y.y = (v.y - mean) * rstd * gv.y + bv.y;
    y.z = (v.z - mean) * rstd * gv.z + bv.z;
    y.w = (v.w - mean) * rstd * gv.w + bv.w;
    *(float4*)(Y + (size_t)row * DM + (tid << 2)) = y;
}

// =====================================================================
extern "C" void kernel_launch(void* const* d_in, const int* in_sizes, int n_in,
                              void* d_out, int out_size)
{
    const float* z_in = (const float*)d_in[0];
    const float* Wq = (const float*)d_in[1];
    const float* bq = (const float*)d_in[2];
    const float* Wk = (const float*)d_in[3];
    const float* bk = (const float*)d_in[4];
    const float* Wv = (const float*)d_in[5];
    const float* bv = (const float*)d_in[6];
    const float* Wo = (const float*)d_in[7];
    const float* bo = (const float*)d_in[8];
    const float* W1 = (const float*)d_in[9];
    const float* b1 = (const float*)d_in[10];
    const float* W2 = (const float*)d_in[11];
    const float* b2 = (const float*)d_in[12];
    const float* g1 = (const float*)d_in[13];
    const float* be1 = (const float*)d_in[14];
    const float* g2 = (const float*)d_in[15];
    const float* be2 = (const float*)d_in[16];
    float* out = (float*)d_out;

    float *Qb, *Kb, *Vb, *Ob, *Tb, *Zb, *H1b;
    float *WqTb, *WkTb, *WvTb, *WoTb, *W1Tb, *W2Tb;
    cudaGetSymbolAddress((void**)&Qb, g_Q);
    cudaGetSymbolAddress((void**)&Kb, g_K);
    cudaGetSymbolAddress((void**)&Vb, g_V);
    cudaGetSymbolAddress((void**)&Ob, g_O);
    cudaGetSymbolAddress((void**)&Tb, g_T);
    cudaGetSymbolAddress((void**)&Zb, g_Z);
    cudaGetSymbolAddress((void**)&H1b, g_H1);
    cudaGetSymbolAddress((void**)&WqTb, g_WqT);
    cudaGetSymbolAddress((void**)&WkTb, g_WkT);
    cudaGetSymbolAddress((void**)&WvTb, g_WvT);
    cudaGetSymbolAddress((void**)&WoTb, g_WoT);
    cudaGetSymbolAddress((void**)&W1Tb, g_W1T);
    cudaGetSymbolAddress((void**)&W2Tb, g_W2T);

    cudaFuncSetAttribute(attn_mma,
        cudaFuncAttributeMaxDynamicSharedMemorySize, ATTN_SMEM_BYTES);
    cudaFuncSetAttribute(mma_gemm<false, false>,
        cudaFuncAttributeMaxDynamicSharedMemorySize, G_SMEM_BYTES);
    cudaFuncSetAttribute(mma_gemm<false, true>,
        cudaFuncAttributeMaxDynamicSharedMemorySize, G_SMEM_BYTES);
    cudaFuncSetAttribute(mma_gemm<true, false>,
        cudaFuncAttributeMaxDynamicSharedMemorySize, G_SMEM_BYTES);

    // weight pre-transposes
    headed_T_kernel<<<(DM * DM) / 256, 256>>>(Wq, WqTb);
    headed_T_kernel<<<(DM * DM) / 256, 256>>>(Wk, WkTb);
    headed_T_kernel<<<(DM * DM) / 256, 256>>>(Wv, WvTb);
    matT_kernel<<<(DM * DM + 255) / 256, 256>>>(Wo, WoTb, DM, DM);
    matT_kernel<<<(DM * DFF + 255) / 256, 256>>>(W1, W1Tb, DM, DFF);
    matT_kernel<<<(DFF * DM + 255) / 256, 256>>>(W2, W2Tb, DFF, DM);

    dim3 blk(256);
    dim3 gP (DM  / 128, ROWS / 128);   // (4, 32)
    dim3 gF1(DFF / 128, ROWS / 128);   // (16, 32)
    dim3 gAttn(SEQ / 128, NH, BB);     // (16, 8, 2)

    for (int it = 0; it < 4; it++) {
        const float* z = (it == 0) ? z_in : Zb;

        mma_gemm<false, false><<<gP, blk, G_SMEM_BYTES>>>(z, WqTb, bq, nullptr, Qb, ROWS, DM, DM);
        mma_gemm<false, false><<<gP, blk, G_SMEM_BYTES>>>(z, WkTb, bk, nullptr, Kb, ROWS, DM, DM);
        mma_gemm<false, false><<<gP, blk, G_SMEM_BYTES>>>(z, WvTb, bv, nullptr, Vb, ROWS, DM, DM);

        attn_mma<<<gAttn, blk, ATTN_SMEM_BYTES>>>(Qb, Kb, Vb, Ob);

        mma_gemm<false, true><<<gP, blk, G_SMEM_BYTES>>>(Ob, WoTb, bo, z, Tb, ROWS, DM, DM);

        float* lnout = (it == 3) ? out : Zb;
        ln_kernel<<<ROWS, 128>>>(Tb, g1, be1, lnout);

        if (it < 3) {
            mma_gemm<true, false><<<gF1, blk, G_SMEM_BYTES>>>(Zb, W1Tb, b1, nullptr, H1b, ROWS, DFF, DM);
            mma_gemm<false, true><<<gP, blk, G_SMEM_BYTES>>>(H1b, W2Tb, b2, Zb, Tb, ROWS, DM, DFF);
            ln_kernel<<<ROWS, 128>>>(Tb, g2, be2, Zb);
        }
    }
}

// round 5
// speedup vs baseline: 3.4533x; 1.1103x over previous
#include <cuda_runtime.h>
#include <cstdint>
#include <math.h>

#define DM   512
#define DFF  2048
#define NH   8
#define DH   64
#define BB   2
#define SEQ  2048
#define ROWS (BB*SEQ)   // 4096
#define QKV_LD 1536

// ---------------- static scratch (no allocations allowed) ----------------
__device__ float    g_QKV [ROWS*QKV_LD];
__device__ float    g_O   [ROWS*DM];
__device__ float    g_T   [ROWS*DM];
__device__ float    g_Z   [ROWS*DM];
__device__ float    g_H1  [ROWS*DFF];
__device__ uint32_t g_WqkvT[QKV_LD*DM];   // tf32 bits, [n][k]
__device__ uint32_t g_WoT [DM*DM];
__device__ uint32_t g_W1T [DFF*DM];
__device__ uint32_t g_W2T [DM*DFF];
__device__ float    g_bqkv[QKV_LD];

__device__ __forceinline__ uint32_t f2tf32(float f) {
    uint32_t r;
    asm("cvt.rna.tf32.f32 %0, %1;" : "=r"(r) : "f"(f));
    return r;
}

#define MMA_TF32(d0,d1,d2,d3, a0,a1,a2,a3, b0,b1) \
    asm volatile("mma.sync.aligned.m16n8k8.row.col.f32.tf32.tf32.f32 " \
        "{%0,%1,%2,%3}, {%4,%5,%6,%7}, {%8,%9}, {%0,%1,%2,%3};" \
        : "+f"(d0), "+f"(d1), "+f"(d2), "+f"(d3) \
        : "r"(a0), "r"(a1), "r"(a2), "r"(a3), "r"(b0), "r"(b1))

// =====================================================================
// prep_weights: all transposes + tf32 conversion + bias concat, 1 launch.
// blockIdx.y selects target matrix.
// =====================================================================
__global__ void prep_weights(
    const float* __restrict__ Wq, const float* __restrict__ Wk,
    const float* __restrict__ Wv, const float* __restrict__ Wo,
    const float* __restrict__ W1, const float* __restrict__ W2,
    const float* __restrict__ bq, const float* __restrict__ bk,
    const float* __restrict__ bv,
    uint32_t* __restrict__ QKVT, uint32_t* __restrict__ WoT,
    uint32_t* __restrict__ W1T,  uint32_t* __restrict__ W2T,
    float* __restrict__ bqkv)
{
    int idx = blockIdx.x * 256 + threadIdx.x;
    switch (blockIdx.y) {
    case 0: {   // QKV headed weights -> [1536][512] tf32
        if (idx >= QKV_LD * DM) return;
        int n = idx >> 9, k = idx & 511;
        const float* W = (n < 512) ? Wq : ((n < 1024) ? Wk : Wv);
        int nl = n & 511;
        QKVT[idx] = f2tf32(W[((size_t)(nl >> 6) * 512 + k) * 64 + (nl & 63)]);
    } break;
    case 1: {   // Wo [512,512] -> [n][k]
        if (idx >= DM * DM) return;
        int n = idx >> 9, k = idx & 511;
        WoT[idx] = f2tf32(Wo[(size_t)k * DM + n]);
    } break;
    case 2: {   // W1 [512,2048] -> [2048][512]
        if (idx >= DFF * DM) return;
        int n = idx >> 9, k = idx & 511;
        W1T[idx] = f2tf32(W1[(size_t)k * DFF + n]);
    } break;
    case 3: {   // W2 [2048,512] -> [512][2048]
        if (idx >= DM * DFF) return;
        int n = idx >> 11, k = idx & 2047;
        W2T[idx] = f2tf32(W2[(size_t)k * DM + n]);
    } break;
    case 4: {   // bias concat
        if (idx >= 512) return;
        bqkv[idx]        = bq[idx];
        bqkv[512 + idx]  = bk[idx];
        bqkv[1024 + idx] = bv[idx];
    } break;
    }
}

// =====================================================================
// TF32 mma.sync GEMM: C[M,N] = A[M,K] @ BT[N,K]^T + bias (+res)(+relu)
// BT is pre-converted tf32 bits. A converted on the fly.
// CTA 128x128, K-slab 32, double-buffered smem with register prefetch.
// =====================================================================
#define G_SMEM_BYTES (2 * 2 * 128 * 32 * 4)   // 65536

template<bool RELU, bool RES>
__global__ void __launch_bounds__(256) mma_gemm(
    const float* __restrict__ A, const uint32_t* __restrict__ BT,
    const float* __restrict__ bias, const float* __restrict__ R,
    float* __restrict__ C, int M, int N, int K)
{
    extern __shared__ uint32_t sm[];
    uint32_t* Asm = sm;                 // [2][4096]
    uint32_t* Bsm = sm + 8192;          // [2][4096]

    const int tid = threadIdx.x;
    const int wid = tid >> 5, l = tid & 31;
    const int lr  = l >> 2, la = l & 3;
    const int sx  = lr << 2;
    const int wm  = wid & 1;
    const int wn  = wid >> 1;
    const int m0  = blockIdx.y * 128;
    const int n0  = blockIdx.x * 128;

    const int ldr = tid >> 3;
    const int ldc = (tid & 7) << 2;

    float acc[4][4][4] = {};
    const int NS = K >> 5;

    {
        const float*    Ap = A  + (size_t)m0 * K;
        const uint32_t* Bp = BT + (size_t)n0 * K;
#pragma unroll
        for (int i = 0; i < 4; i++) {
            int r = ldr + (i << 5);
            uint32_t idx = r * 32 + (ldc ^ ((r & 7) << 2));
            float4 va = *(const float4*)(Ap + (size_t)r * K + ldc);
            *(uint4*)&Asm[idx] = make_uint4(f2tf32(va.x), f2tf32(va.y), f2tf32(va.z), f2tf32(va.w));
            *(uint4*)&Bsm[idx] = *(const uint4*)(Bp + (size_t)r * K + ldc);
        }
    }
    __syncthreads();

    for (int s = 0; s < NS; s++) {
        const int cur = s & 1;
        const int nxt = cur ^ 1;
        const uint32_t* Ab = Asm + cur * 4096;
        const uint32_t* Bb = Bsm + cur * 4096;

        float4 ra[4]; uint4 rb[4];
        if (s + 1 < NS) {
            const float*    Ap = A  + (size_t)m0 * K + (s + 1) * 32;
            const uint32_t* Bp = BT + (size_t)n0 * K + (s + 1) * 32;
#pragma unroll
            for (int i = 0; i < 4; i++) {
                int r = ldr + (i << 5);
                ra[i] = *(const float4*)(Ap + (size_t)r * K + ldc);
                rb[i] = *(const uint4*)(Bp + (size_t)r * K + ldc);
            }
        }

#pragma unroll
        for (int kc = 0; kc < 32; kc += 8) {
            uint32_t a[4][4], b[4][2];
#pragma unroll
            for (int i = 0; i < 4; i++) {
                const uint32_t* p0 = Ab + (wm * 64 + i * 16 + lr) * 32;
                const uint32_t* p8 = p0 + 8 * 32;
                a[i][0] = p0[(kc + la)     ^ sx];
                a[i][1] = p8[(kc + la)     ^ sx];
                a[i][2] = p0[(kc + la + 4) ^ sx];
                a[i][3] = p8[(kc + la + 4) ^ sx];
            }
#pragma unroll
            for (int j = 0; j < 4; j++) {
                const uint32_t* pb = Bb + (wn * 32 + j * 8 + lr) * 32;
                b[j][0] = pb[(kc + la)     ^ sx];
                b[j][1] = pb[(kc + la + 4) ^ sx];
            }
#pragma unroll
            for (int i = 0; i < 4; i++)
#pragma unroll
                for (int j = 0; j < 4; j++)
                    MMA_TF32(acc[i][j][0], acc[i][j][1], acc[i][j][2], acc[i][j][3],
                             a[i][0], a[i][1], a[i][2], a[i][3], b[j][0], b[j][1]);
        }

        if (s + 1 < NS) {
            uint32_t* An = Asm + nxt * 4096;
            uint32_t* Bn = Bsm + nxt * 4096;
#pragma unroll
            for (int i = 0; i < 4; i++) {
                int r = ldr + (i << 5);
                uint32_t idx = r * 32 + (ldc ^ ((r & 7) << 2));
                *(uint4*)&An[idx] = make_uint4(f2tf32(ra[i].x), f2tf32(ra[i].y),
                                               f2tf32(ra[i].z), f2tf32(ra[i].w));
                *(uint4*)&Bn[idx] = rb[i];
            }
            __syncthreads();
        }
    }

#pragma unroll
    for (int i = 0; i < 4; i++) {
        int mlo = m0 + wm * 64 + i * 16 + lr;
#pragma unroll
        for (int j = 0; j < 4; j++) {
            int n = n0 + wn * 32 + j * 8 + la * 2;
            float2 bz = *(const float2*)(bias + n);
            float2 v0 = make_float2(acc[i][j][0] + bz.x, acc[i][j][1] + bz.y);
            float2 v1 = make_float2(acc[i][j][2] + bz.x, acc[i][j][3] + bz.y);
            if (RES) {
                float2 r0 = *(const float2*)(R + (size_t)mlo * N + n);
                float2 r1 = *(const float2*)(R + (size_t)(mlo + 8) * N + n);
                v0.x += r0.x; v0.y += r0.y; v1.x += r1.x; v1.y += r1.y;
            }
            if (RELU) {
                v0.x = fmaxf(v0.x, 0.f); v0.y = fmaxf(v0.y, 0.f);
                v1.x = fmaxf(v1.x, 0.f); v1.y = fmaxf(v1.y, 0.f);
            }
            *(float2*)(C + (size_t)mlo * N + n) = v0;
            *(float2*)(C + (size_t)(mlo + 8) * N + n) = v1;
        }
    }
}

// =====================================================================
// Flash attention with mma.sync tf32, reading fused QKV buffer.
// CTA = 128 q-rows x one (b,h). V stored TRANSPOSED in smem (Vt[dim][key])
// for conflict-free PV b-fragment loads.
// =====================================================================
#define APAD 68
#define A_QP 0
#define A_K  (128*APAD)
#define A_V  (128*APAD + 64*APAD)
#define ATTN_SMEM_BYTES ((128*APAD + 64*APAD + 64*APAD) * 4)   // 69632

__global__ void __launch_bounds__(256, 2) attn_mma(
    const float* __restrict__ QKV, float* __restrict__ O)
{
    extern __shared__ uint32_t as[];
    uint32_t* QP = as + A_QP;
    uint32_t* Ks = as + A_K;
    uint32_t* Vt = as + A_V;

    const int tid = threadIdx.x;
    const int wid = tid >> 5, l = tid & 31;
    const int lr = l >> 2, la = l & 3;
    const int q0 = blockIdx.x * 128;
    const int h  = blockIdx.y, b = blockIdx.z;
    const size_t rb0 = (size_t)b * SEQ;
    const int hc = h * DH;

    // ---- stage Q (scaled by 1/8, exact) ----
    {
        int r = tid >> 1, c0 = (tid & 1) * 32;
        const float* src = QKV + (rb0 + q0 + r) * QKV_LD + hc + c0;
        uint32_t* dst = QP + r * APAD + c0;
#pragma unroll
        for (int i = 0; i < 8; i++) {
            float4 v = *(const float4*)(src + i * 4);
            dst[i*4+0] = f2tf32(v.x * 0.125f);
            dst[i*4+1] = f2tf32(v.y * 0.125f);
            dst[i*4+2] = f2tf32(v.z * 0.125f);
            dst[i*4+3] = f2tf32(v.w * 0.125f);
        }
    }
    __syncthreads();

    // ---- Q a-fragments into registers ----
    uint32_t aq[8][4];
    {
        const uint32_t* q0p = QP + (wid * 16 + lr) * APAD;
        const uint32_t* q8p = q0p + 8 * APAD;
#pragma unroll
        for (int k = 0; k < 8; k++) {
            aq[k][0] = q0p[k*8 + la];
            aq[k][1] = q8p[k*8 + la];
            aq[k][2] = q0p[k*8 + la + 4];
            aq[k][3] = q8p[k*8 + la + 4];
        }
    }
    // QP rows [wid*16, wid*16+16) now owned by this warp for P staging.

    float o[8][4] = {};
    float m_lo = -1e30f, m_hi = -1e30f, l_lo = 0.f, l_hi = 0.f;

    for (int j0 = 0; j0 < SEQ; j0 += 64) {
        __syncthreads();   // previous tile's smem reads done
        // ---- stage K (row-major) and V (transposed) tiles ----
        {
            int r = tid >> 2, cb = (tid & 3) << 2;
            const float* ksrc = QKV + (rb0 + j0 + r) * QKV_LD + 512  + hc;
            const float* vsrc = QKV + (rb0 + j0 + r) * QKV_LD + 1024 + hc;
            uint32_t* kd = Ks + r * APAD;
#pragma unroll
            for (int i = 0; i < 4; i++) {
                int c = cb + i * 16;
                float4 kv = *(const float4*)(ksrc + c);
                kd[c+0] = f2tf32(kv.x); kd[c+1] = f2tf32(kv.y);
                kd[c+2] = f2tf32(kv.z); kd[c+3] = f2tf32(kv.w);
                float4 vv = *(const float4*)(vsrc + c);
                Vt[(c+0)*APAD + r] = f2tf32(vv.x);
                Vt[(c+1)*APAD + r] = f2tf32(vv.y);
                Vt[(c+2)*APAD + r] = f2tf32(vv.z);
                Vt[(c+3)*APAD + r] = f2tf32(vv.w);
            }
        }
        __syncthreads();

        // ---- S = Q K^T (pre-scaled) ----
        float s[8][4] = {};
#pragma unroll
        for (int k = 0; k < 8; k++) {
#pragma unroll
            for (int j = 0; j < 8; j++) {
                const uint32_t* kb = Ks + (j*8 + lr) * APAD + k*8;
                uint32_t b0 = kb[la], b1 = kb[la + 4];
                MMA_TF32(s[j][0], s[j][1], s[j][2], s[j][3],
                         aq[k][0], aq[k][1], aq[k][2], aq[k][3], b0, b1);
            }
        }

        // ---- online softmax (rows lr and lr+8) ----
        float tml = -1e30f, tmh = -1e30f;
#pragma unroll
        for (int j = 0; j < 8; j++) {
            tml = fmaxf(tml, fmaxf(s[j][0], s[j][1]));
            tmh = fmaxf(tmh, fmaxf(s[j][2], s[j][3]));
        }
        tml = fmaxf(tml, __shfl_xor_sync(0xFFFFFFFFu, tml, 1));
        tml = fmaxf(tml, __shfl_xor_sync(0xFFFFFFFFu, tml, 2));
        tmh = fmaxf(tmh, __shfl_xor_sync(0xFFFFFFFFu, tmh, 1));
        tmh = fmaxf(tmh, __shfl_xor_sync(0xFFFFFFFFu, tmh, 2));
        float mnl = fmaxf(m_lo, tml), mnh = fmaxf(m_hi, tmh);
        float cfl = __expf(m_lo - mnl), cfh = __expf(m_hi - mnh);
        m_lo = mnl; m_hi = mnh;

        float suml = 0.f, sumh = 0.f;
#pragma unroll
        for (int j = 0; j < 8; j++) {
            s[j][0] = __expf(s[j][0] - mnl); suml += s[j][0];
            s[j][1] = __expf(s[j][1] - mnl); suml += s[j][1];
            s[j][2] = __expf(s[j][2] - mnh); sumh += s[j][2];
            s[j][3] = __expf(s[j][3] - mnh); sumh += s[j][3];
        }
        suml += __shfl_xor_sync(0xFFFFFFFFu, suml, 1);
        suml += __shfl_xor_sync(0xFFFFFFFFu, suml, 2);
        sumh += __shfl_xor_sync(0xFFFFFFFFu, sumh, 1);
        sumh += __shfl_xor_sync(0xFFFFFFFFu, sumh, 2);
        l_lo = l_lo * cfl + suml;
        l_hi = l_hi * cfh + sumh;

#pragma unroll
        for (int j = 0; j < 8; j++) {
            o[j][0] *= cfl; o[j][1] *= cfl;
            o[j][2] *= cfh; o[j][3] *= cfh;
        }

        // ---- stage P into warp-owned rows of QP ----
        uint32_t* p0w = QP + (wid * 16 + lr) * APAD;
        uint32_t* p8w = p0w + 8 * APAD;
#pragma unroll
        for (int j = 0; j < 8; j++) {
            p0w[j*8 + 2*la]     = f2tf32(s[j][0]);
            p0w[j*8 + 2*la + 1] = f2tf32(s[j][1]);
            p8w[j*8 + 2*la]     = f2tf32(s[j][2]);
            p8w[j*8 + 2*la + 1] = f2tf32(s[j][3]);
        }
        __syncwarp();

        // ---- O += P @ V  (Vt conflict-free b-fragments) ----
#pragma unroll
        for (int k = 0; k < 8; k++) {
            uint32_t ap0 = p0w[k*8 + la];
            uint32_t ap1 = p8w[k*8 + la];
            uint32_t ap2 = p0w[k*8 + la + 4];
            uint32_t ap3 = p8w[k*8 + la + 4];
#pragma unroll
            for (int j = 0; j < 8; j++) {
                uint32_t b0 = Vt[(j*8 + lr) * APAD + k*8 + la];
                uint32_t b1 = Vt[(j*8 + lr) * APAD + k*8 + la + 4];
                MMA_TF32(o[j][0], o[j][1], o[j][2], o[j][3],
                         ap0, ap1, ap2, ap3, b0, b1);
            }
        }
    }

    // ---- epilogue ----
    float invl = 1.f / l_lo, invh = 1.f / l_hi;
    float* d0 = O + (rb0 + q0 + wid * 16 + lr) * DM + hc;
    float* d8 = d0 + 8 * DM;
#pragma unroll
    for (int j = 0; j < 8; j++) {
        *(float2*)(d0 + j*8 + 2*la) = make_float2(o[j][0] * invl, o[j][1] * invl);
        *(float2*)(d8 + j*8 + 2*la) = make_float2(o[j][2] * invh, o[j][3] * invh);
    }
}

// =====================================================================
// LayerNorm: warp per row, 8 rows per 256-thread block. grid = 512.
// =====================================================================
__global__ void __launch_bounds__(256) ln_kernel(
    const float* __restrict__ X, const float* __restrict__ g,
    const float* __restrict__ be, float* __restrict__ Y)
{
    const int row = blockIdx.x * 8 + (threadIdx.x >> 5);
    const int l = threadIdx.x & 31;
    const float* x = X + (size_t)row * DM + l * 4;

    float4 v[4];
    float s = 0.f, q = 0.f;
#pragma unroll
    for (int i = 0; i < 4; i++) {
        v[i] = *(const float4*)(x + i * 128);
        s += v[i].x + v[i].y + v[i].z + v[i].w;
        q += v[i].x * v[i].x + v[i].y * v[i].y + v[i].z * v[i].z + v[i].w * v[i].w;
    }
#pragma unroll
    for (int o = 16; o; o >>= 1) {
        s += __shfl_xor_sync(0xFFFFFFFFu, s, o);
        q += __shfl_xor_sync(0xFFFFFFFFu, q, o);
    }
    float mean = s * (1.f / DM);
    float var  = q * (1.f / DM) - mean * mean;
    float rstd = rsqrtf(var + 1e-5f);

    float* y = Y + (size_t)row * DM + l * 4;
#pragma unroll
    for (int i = 0; i < 4; i++) {
        float4 gv = *(const float4*)(g  + l * 4 + i * 128);
        float4 bv = *(const float4*)(be + l * 4 + i * 128);
        float4 r;
        r.x = (v[i].x - mean) * rstd * gv.x + bv.x;
        r.y = (v[i].y - mean) * rstd * gv.y + bv.y;
        r.z = (v[i].z - mean) * rstd * gv.z + bv.z;
        r.w = (v[i].w - mean) * rstd * gv.w + bv.w;
        *(float4*)(y + i * 128) = r;
    }
}

// =====================================================================
extern "C" void kernel_launch(void* const* d_in, const int* in_sizes, int n_in,
                              void* d_out, int out_size)
{
    const float* z_in = (const float*)d_in[0];
    const float* Wq = (const float*)d_in[1];
    const float* bq = (const float*)d_in[2];
    const float* Wk = (const float*)d_in[3];
    const float* bk = (const float*)d_in[4];
    const float* Wv = (const float*)d_in[5];
    const float* bv = (const float*)d_in[6];
    const float* Wo = (const float*)d_in[7];
    const float* bo = (const float*)d_in[8];
    const float* W1 = (const float*)d_in[9];
    const float* b1 = (const float*)d_in[10];
    const float* W2 = (const float*)d_in[11];
    const float* b2 = (const float*)d_in[12];
    const float* g1 = (const float*)d_in[13];
    const float* be1 = (const float*)d_in[14];
    const float* g2 = (const float*)d_in[15];
    const float* be2 = (const float*)d_in[16];
    float* out = (float*)d_out;

    float *QKVb, *Ob, *Tb, *Zb, *H1b, *bqkvb;
    uint32_t *WqkvTb, *WoTb, *W1Tb, *W2Tb;
    cudaGetSymbolAddress((void**)&QKVb, g_QKV);
    cudaGetSymbolAddress((void**)&Ob, g_O);
    cudaGetSymbolAddress((void**)&Tb, g_T);
    cudaGetSymbolAddress((void**)&Zb, g_Z);
    cudaGetSymbolAddress((void**)&H1b, g_H1);
    cudaGetSymbolAddress((void**)&WqkvTb, g_WqkvT);
    cudaGetSymbolAddress((void**)&WoTb, g_WoT);
    cudaGetSymbolAddress((void**)&W1Tb, g_W1T);
    cudaGetSymbolAddress((void**)&W2Tb, g_W2T);
    cudaGetSymbolAddress((void**)&bqkvb, g_bqkv);

    cudaFuncSetAttribute(attn_mma,
        cudaFuncAttributeMaxDynamicSharedMemorySize, ATTN_SMEM_BYTES);
    cudaFuncSetAttribute(mma_gemm<false, false>,
        cudaFuncAttributeMaxDynamicSharedMemorySize, G_SMEM_BYTES);
    cudaFuncSetAttribute(mma_gemm<false, true>,
        cudaFuncAttributeMaxDynamicSharedMemorySize, G_SMEM_BYTES);
    cudaFuncSetAttribute(mma_gemm<true, false>,
        cudaFuncAttributeMaxDynamicSharedMemorySize, G_SMEM_BYTES);

    // one prep launch: all transposes + tf32 conversion + bias concat
    prep_weights<<<dim3(4096, 5), 256>>>(Wq, Wk, Wv, Wo, W1, W2, bq, bk, bv,
                                         WqkvTb, WoTb, W1Tb, W2Tb, bqkvb);

    dim3 blk(256);
    dim3 gQKV(QKV_LD / 128, ROWS / 128);   // (12, 32) fused QKV
    dim3 gP  (DM  / 128, ROWS / 128);      // (4, 32)
    dim3 gF1 (DFF / 128, ROWS / 128);      // (16, 32)
    dim3 gAttn(SEQ / 128, NH, BB);         // (16, 8, 2)

    for (int it = 0; it < 4; it++) {
        const float* z = (it == 0) ? z_in : Zb;

        mma_gemm<false, false><<<gQKV, blk, G_SMEM_BYTES>>>(z, WqkvTb, bqkvb, nullptr, QKVb, ROWS, QKV_LD, DM);

        attn_mma<<<gAttn, blk, ATTN_SMEM_BYTES>>>(QKVb, Ob);

        mma_gemm<false, true><<<gP, blk, G_SMEM_BYTES>>>(Ob, WoTb, bo, z, Tb, ROWS, DM, DM);

        float* lnout = (it == 3) ? out : Zb;
        ln_kernel<<<ROWS / 8, 256>>>(Tb, g1, be1, lnout);

        if (it < 3) {
            mma_gemm<true, false><<<gF1, blk, G_SMEM_BYTES>>>(Zb, W1Tb, b1, nullptr, H1b, ROWS, DFF, DM);
            mma_gemm<false, true><<<gP, blk, G_SMEM_BYTES>>>(H1b, W2Tb, b2, Zb, Tb, ROWS, DM, DFF);
            ln_kernel<<<ROWS / 8, 256>>>(Tb, g2, be2, Zb);
        }
    }
}